// round 6
// baseline (speedup 1.0000x reference)
#include <cuda_runtime.h>
#include <cuda_bf16.h>
#include <stdint.h>

// Problem constants
#define BN   32
#define CI   128
#define CO   256
#define HH   56
#define WW   56
#define EE   4
#define RR   16
#define HW   (HH*WW)        // 3136
#define KVOL 9
#define CIK  (CI*KVOL)      // 1152
#define PERB (CO*CI*KVOL)   // 294912
#define PERB4 (PERB/4)

__device__ float g_gap[BN*CI];
__device__ float g_rout[BN*EE];
__device__ float g_kern[BN*CO*CI*KVOL];   // 37.7 MB mixed kernels

// packed fp32x2 fma: d = a*b + d (both halves independently)
__device__ __forceinline__ void ffma2(unsigned long long& d,
                                      unsigned long long a,
                                      unsigned long long b) {
    asm("fma.rn.f32x2 %0, %1, %2, %0;" : "+l"(d) : "l"(a), "l"(b));
}

// ---------------------------------------------------------------------------
// Kernel 1: global average pool
// ---------------------------------------------------------------------------
__global__ void gap_kernel(const float* __restrict__ x) {
    int bc = blockIdx.x;
    const float* p = x + (size_t)bc * HW;
    float s = 0.f;
    for (int i = threadIdx.x; i < HW; i += 256) s += p[i];
    __shared__ float red[256];
    red[threadIdx.x] = s;
    __syncthreads();
    for (int o = 128; o > 0; o >>= 1) {
        if (threadIdx.x < o) red[threadIdx.x] += red[threadIdx.x + o];
        __syncthreads();
    }
    if (threadIdx.x == 0) g_gap[bc] = red[0] * (1.0f / (float)HW);
}

// ---------------------------------------------------------------------------
// Kernel 2: router MLP + softmax(logits/30)
// ---------------------------------------------------------------------------
__global__ void rout_kernel(const float* __restrict__ w1, const float* __restrict__ b1,
                            const float* __restrict__ w2, const float* __restrict__ b2) {
    int b = threadIdx.x;
    if (b >= BN) return;
    float h[RR];
    #pragma unroll
    for (int j = 0; j < RR; ++j) {
        float s = b1[j];
        for (int i = 0; i < CI; ++i) s += w1[j*CI + i] * g_gap[b*CI + i];
        h[j] = fmaxf(s, 0.f);
    }
    float lg[EE];
    float mx = -1e30f;
    #pragma unroll
    for (int e = 0; e < EE; ++e) {
        float s = b2[e];
        #pragma unroll
        for (int j = 0; j < RR; ++j) s += w2[e*RR + j] * h[j];
        lg[e] = s * (1.0f / 30.0f);
        mx = fmaxf(mx, lg[e]);
    }
    float den = 0.f;
    #pragma unroll
    for (int e = 0; e < EE; ++e) { lg[e] = __expf(lg[e] - mx); den += lg[e]; }
    float inv = 1.0f / den;
    #pragma unroll
    for (int e = 0; e < EE; ++e) g_rout[b*EE + e] = lg[e] * inv;
}

// ---------------------------------------------------------------------------
// Kernel 3: mix expert banks
// ---------------------------------------------------------------------------
__global__ void mix_kernel(const float* __restrict__ convs) {
    int idx = blockIdx.x * blockDim.x + threadIdx.x;
    const int total = BN * PERB4;
    if (idx >= total) return;
    int b = idx / PERB4;
    int j = idx - b * PERB4;
    float r0 = g_rout[b*EE + 0];
    float r1 = g_rout[b*EE + 1];
    float r2 = g_rout[b*EE + 2];
    float r3 = g_rout[b*EE + 3];
    const float4* c4 = (const float4*)convs;
    float4 a = c4[0*PERB4 + j];
    float4 bb = c4[1*PERB4 + j];
    float4 c = c4[2*PERB4 + j];
    float4 d = c4[3*PERB4 + j];
    float4 o;
    o.x = r0*a.x + r1*bb.x + r2*c.x + r3*d.x;
    o.y = r0*a.y + r1*bb.y + r2*c.y + r3*d.y;
    o.z = r0*a.z + r1*bb.z + r2*c.z + r3*d.z;
    o.w = r0*a.w + r1*bb.w + r2*c.w + r3*d.w;
    ((float4*)g_kern)[idx] = o;
}

// ---------------------------------------------------------------------------
// Kernel 4: direct 3x3 conv with packed f32x2 FMA.
// Tile: b x (32 couts) x (8 output rows x 56 cols).
// The two f32x2 halves are output rows (r, r+4).
// x staged row-PAIRED in SMEM: xsp[ci][i][col] = {x[oh_base+i-1], x[oh_base+i+3]}
// Weights staged splat-packed {w,w} (64-bit) in SMEM.
// 256 threads = 8 warps; warp handles 4 couts; lane = rowpair(4) x colgroup(8),
// 7 pixels per lane per row => acc = 4 couts x 7 f32x2 pairs.
// ---------------------------------------------------------------------------
#define CIC    4
#define NCHNK  (CI/CIC)     // 32
#define OROWS  8            // output rows per block
#define XCOLS  59           // 58 halo cols + 1 pad (bank spread)
#define COT    32           // couts per block
#define TCO    4            // couts per warp
#define TPX    7

__global__ void __launch_bounds__(256)
conv_kernel(const float* __restrict__ x, float* __restrict__ out) {
    __shared__ unsigned long long xsp[CIC][6][XCOLS];   // row-paired x, 11.3 KB
    __shared__ unsigned long long wsp[COT*CIC*KVOL];    // splat weights, 9.2 KB

    const int b       = blockIdx.z;
    const int co_base = blockIdx.y * COT;
    const int oh_base = blockIdx.x * OROWS;
    const int t  = threadIdx.x;
    const int g  = t & 31;
    const int cg = t >> 5;                  // warp id -> cout group
    const int rp = g >> 3;                  // row-pair 0..3 (rows rp, rp+4)
    const int c0 = (g & 7) * TPX;           // col base

    unsigned long long acc[TCO][TPX];
    #pragma unroll
    for (int u = 0; u < TCO; ++u)
        #pragma unroll
        for (int j = 0; j < TPX; ++j) acc[u][j] = 0ULL;

    const float* xb = x + (size_t)b * CI * HW;
    const float* kb = g_kern + ((size_t)b * CO + co_base) * CIK;

    for (int cc = 0; cc < NCHNK; ++cc) {
        const int ci0 = cc * CIC;
        // stage x: CIC * 6 paired-rows * 58 cols; pair = (row i, row i+4)
        for (int m = t; m < CIC*6*58; m += 256) {
            int ci  = m / (6*58);
            int rem = m - ci*(6*58);
            int row = rem / 58;             // paired-row index 0..5
            int col = rem - row*58;
            int gh0 = oh_base + row - 1;    // first half row
            int gh1 = gh0 + 4;              // second half row
            int gw  = col - 1;
            float v0 = 0.f, v1 = 0.f;
            if ((unsigned)gw < WW) {
                const float* xc = xb + (ci0 + ci)*HW + gw;
                if ((unsigned)gh0 < HH) v0 = xc[gh0*WW];
                if ((unsigned)gh1 < HH) v1 = xc[gh1*WW];
            }
            unsigned long long pk = (unsigned long long)__float_as_uint(v0)
                                  | ((unsigned long long)__float_as_uint(v1) << 32);
            xsp[ci][row][col] = pk;
        }
        // stage weights splat-packed: 32co * 4ci * 9 = 1152
        for (int m = t; m < COT*CIC*KVOL; m += 256) {
            int co  = m / (CIC*KVOL);
            int rem = m - co*(CIC*KVOL);    // ci*9 + k
            float w = kb[co*CIK + ci0*KVOL + rem];
            unsigned long long pw = (unsigned long long)__float_as_uint(w);
            wsp[m] = pw | (pw << 32);
        }
        __syncthreads();

        const unsigned long long* wt = wsp + cg * TCO * (CIC*KVOL);
        #pragma unroll 1
        for (int ci = 0; ci < CIC; ++ci) {
            #pragma unroll
            for (int kh = 0; kh < 3; ++kh) {
                unsigned long long xv[TPX+2];
                #pragma unroll
                for (int j = 0; j < TPX+2; ++j) xv[j] = xsp[ci][rp+kh][c0+j];
                #pragma unroll
                for (int kw = 0; kw < 3; ++kw) {
                    #pragma unroll
                    for (int u = 0; u < TCO; ++u) {
                        unsigned long long wv = wt[u*(CIC*KVOL) + ci*KVOL + kh*3 + kw];
                        #pragma unroll
                        for (int j = 0; j < TPX; ++j)
                            ffma2(acc[u][j], wv, xv[kw+j]);
                    }
                }
            }
        }
        __syncthreads();
    }

    // write: pair halves are rows (oh_base+rp, oh_base+rp+4)
    #pragma unroll
    for (int u = 0; u < TCO; ++u) {
        int co = co_base + cg*TCO + u;
        float* op0 = out + (((size_t)b*CO + co)*HH + oh_base + rp)*WW + c0;
        float* op1 = op0 + 4*WW;
        #pragma unroll
        for (int j = 0; j < TPX; ++j) {
            unsigned long long a = acc[u][j];
            op0[j] = __uint_as_float((unsigned)(a & 0xffffffffULL));
            op1[j] = __uint_as_float((unsigned)(a >> 32));
        }
    }
}

// ---------------------------------------------------------------------------
extern "C" void kernel_launch(void* const* d_in, const int* in_sizes, int n_in,
                              void* d_out, int out_size) {
    const float* x     = (const float*)d_in[0];
    const float* convs = (const float*)d_in[1];
    const float* w1    = (const float*)d_in[2];
    const float* b1    = (const float*)d_in[3];
    const float* w2    = (const float*)d_in[4];
    const float* b2    = (const float*)d_in[5];
    float* out = (float*)d_out;

    gap_kernel<<<BN*CI, 256>>>(x);
    rout_kernel<<<1, 32>>>(w1, b1, w2, b2);
    {
        const int total = BN * PERB4;
        mix_kernel<<<(total + 255)/256, 256>>>(convs);
    }
    {
        dim3 grid(HH/OROWS, CO/COT, BN);   // 7 x 8 x 32 = 1792
        conv_kernel<<<grid, 256>>>(x, out);
    }
    (void)in_sizes; (void)n_in; (void)out_size;
}

// round 12
// speedup vs baseline: 2.3490x; 2.3490x over previous
#include <cuda_runtime.h>
#include <cuda_bf16.h>
#include <stdint.h>

#define BN   32
#define CI   128
#define CO   256
#define HH   56
#define WW   56
#define EE   4
#define RR   16
#define HW   (HH*WW)        // 3136
#define KVOL 9
#define EOFF (CO*CI*KVOL)

__device__ float g_gap[BN*CI];
__device__ float g_rout[BN*EE];
// tap-major mixed kernels: [b][tap][co][ci]
__device__ float g_kernT[(size_t)BN*KVOL*CO*CI];

__device__ __forceinline__ uint32_t smem_u32(const void* p) {
    uint32_t a;
    asm("{ .reg .u64 t; cvta.to.shared.u64 t, %1; cvt.u32.u64 %0, t; }"
        : "=r"(a) : "l"(p));
    return a;
}
__device__ __forceinline__ uint32_t pk2(__nv_bfloat16 a, __nv_bfloat16 b) {
    unsigned short x = *(unsigned short*)&a, y = *(unsigned short*)&b;
    return (uint32_t)x | ((uint32_t)y << 16);
}
__device__ __forceinline__ void ldsm_x4(uint32_t* r, uint32_t addr) {
    asm volatile("ldmatrix.sync.aligned.m8n8.x4.shared.b16 {%0,%1,%2,%3}, [%4];"
        : "=r"(r[0]), "=r"(r[1]), "=r"(r[2]), "=r"(r[3]) : "r"(addr));
}
__device__ __forceinline__ void ldsm_x2(uint32_t* r, uint32_t addr) {
    asm volatile("ldmatrix.sync.aligned.m8n8.x2.shared.b16 {%0,%1}, [%2];"
        : "=r"(r[0]), "=r"(r[1]) : "r"(addr));
}
__device__ __forceinline__ void mma_bf16(float* d, const uint32_t* a, const uint32_t* b) {
    asm volatile("mma.sync.aligned.m16n8k16.row.col.f32.bf16.bf16.f32 "
        "{%0,%1,%2,%3}, {%4,%5,%6,%7}, {%8,%9}, {%0,%1,%2,%3};"
        : "+f"(d[0]), "+f"(d[1]), "+f"(d[2]), "+f"(d[3])
        : "r"(a[0]), "r"(a[1]), "r"(a[2]), "r"(a[3]), "r"(b[0]), "r"(b[1]));
}

// ---------------------------------------------------------------------------
// Kernel 1: global average pool
// ---------------------------------------------------------------------------
__global__ void gap_kernel(const float* __restrict__ x) {
    int bc = blockIdx.x;
    const float* p = x + (size_t)bc * HW;
    float s = 0.f;
    for (int i = threadIdx.x; i < HW; i += 256) s += p[i];
    __shared__ float red[256];
    red[threadIdx.x] = s;
    __syncthreads();
    for (int o = 128; o > 0; o >>= 1) {
        if (threadIdx.x < o) red[threadIdx.x] += red[threadIdx.x + o];
        __syncthreads();
    }
    if (threadIdx.x == 0) g_gap[bc] = red[0] * (1.0f / (float)HW);
}

// ---------------------------------------------------------------------------
// Kernel 2: router MLP + softmax(logits/30)
// ---------------------------------------------------------------------------
__global__ void rout_kernel(const float* __restrict__ w1, const float* __restrict__ b1,
                            const float* __restrict__ w2, const float* __restrict__ b2) {
    int b = threadIdx.x;
    if (b >= BN) return;
    float h[RR];
    #pragma unroll
    for (int j = 0; j < RR; ++j) {
        float s = b1[j];
        for (int i = 0; i < CI; ++i) s += w1[j*CI + i] * g_gap[b*CI + i];
        h[j] = fmaxf(s, 0.f);
    }
    float lg[EE];
    float mx = -1e30f;
    #pragma unroll
    for (int e = 0; e < EE; ++e) {
        float s = b2[e];
        #pragma unroll
        for (int j = 0; j < RR; ++j) s += w2[e*RR + j] * h[j];
        lg[e] = s * (1.0f / 30.0f);
        mx = fmaxf(mx, lg[e]);
    }
    float den = 0.f;
    #pragma unroll
    for (int e = 0; e < EE; ++e) { lg[e] = __expf(lg[e] - mx); den += lg[e]; }
    float inv = 1.0f / den;
    #pragma unroll
    for (int e = 0; e < EE; ++e) g_rout[b*EE + e] = lg[e] * inv;
}

// ---------------------------------------------------------------------------
// Kernel 3: mix expert banks -> tap-major g_kernT[b][tap][co][ci]
// ---------------------------------------------------------------------------
__global__ void mixT_kernel(const float* __restrict__ convs) {
    int idx = blockIdx.x * blockDim.x + threadIdx.x;
    if (idx >= BN*CO*CI) return;
    int b  = idx / (CO*CI);
    int rm = idx - b * (CO*CI);
    int co = rm / CI;
    int ci = rm - co * CI;
    float r0 = g_rout[b*EE+0], r1 = g_rout[b*EE+1];
    float r2 = g_rout[b*EE+2], r3 = g_rout[b*EE+3];
    const float* s = convs + ((size_t)co * CI + ci) * KVOL;
    #pragma unroll
    for (int tap = 0; tap < KVOL; ++tap) {
        float a = r0 * s[tap] + r1 * s[EOFF + tap]
                + r2 * s[2*EOFF + tap] + r3 * s[3*EOFF + tap];
        g_kernT[(((size_t)b*KVOL + tap)*CO + co)*CI + ci] = a;
    }
}

// ---------------------------------------------------------------------------
// Kernel 4: bf16 mma.sync implicit-GEMM conv, 3-term hi/lo split.
// CTA: 128 couts x 112 px (2 rows x 56), K=1152 tap-major, chunks of 32.
// SMEM per chunk: Ahi/Alo [128][32], Bhi/Blo [112][32] bf16, rows padded to
// 80 B (conflict-free ldmatrix). Warp tile 32co x 56px = 2x7 m16n8k16 frags.
// D += Ahi*Bhi + Alo*Bhi + Ahi*Blo  (fp32 accum in registers).
// ---------------------------------------------------------------------------
#define STR   80          // smem row stride bytes (32 bf16 + 16B pad)
#define OFF_AL 10240
#define OFF_BH 20480
#define OFF_BL 29440

__global__ void __launch_bounds__(256, 2)
conv_mma_kernel(const float* __restrict__ x, float* __restrict__ out) {
    __shared__ __align__(16) unsigned char sm[38400];

    const int b   = blockIdx.z;
    const int co0 = blockIdx.y * 128;
    const int oh0 = blockIdx.x * 2;
    const int t   = threadIdx.x;
    const int L   = t & 31;
    const int w   = t >> 5;
    const int wco = (w & 3) * 32;     // warp cout base within tile
    const int pxw = (w >> 2) * 56;    // warp pixel base (row select)

    const uint32_t sb = smem_u32(sm);
    // per-lane ldmatrix address offsets
    const uint32_t aoff  = (uint32_t)((L % 16) * STR + (L / 16) * 16);
    const uint32_t boff4 = (uint32_t)(((L & 7) + ((L >> 4) & 1) * 8) * STR + ((L >> 3) & 1) * 16);
    const uint32_t boff2 = (uint32_t)((L & 7) * STR + ((L >> 3) & 1) * 16);

    float d[2][7][4];
    #pragma unroll
    for (int mf = 0; mf < 2; ++mf)
        #pragma unroll
        for (int nf = 0; nf < 7; ++nf)
            #pragma unroll
            for (int k = 0; k < 4; ++k) d[mf][nf][k] = 0.f;

    const float* xb = x + (size_t)b * CI * HW;

    for (int c = 0; c < 36; ++c) {
        const int tap = c >> 2;
        const int ci0 = (c & 3) * 32;
        const int kh = tap / 3, kw = tap - 3 * (tap / 3);
        const float* ka = g_kernT + (((size_t)b*KVOL + tap)*CO + co0)*CI + ci0;

        // ---- stage A (128co x 32ci), hi/lo, as 16-bit pairs ----
        #pragma unroll
        for (int i = 0; i < 8; ++i) {
            int m = t + i*256;              // 0..2047 pairs
            int co = m >> 4, cip = m & 15;
            float2 v = *(const float2*)(ka + co*CI + cip*2);
            __nv_bfloat16 h0 = __float2bfloat16(v.x);
            __nv_bfloat16 h1 = __float2bfloat16(v.y);
            __nv_bfloat16 l0 = __float2bfloat16(v.x - __bfloat162float(h0));
            __nv_bfloat16 l1 = __float2bfloat16(v.y - __bfloat162float(h1));
            uint32_t byo = (uint32_t)(co*STR + cip*4);
            *(uint32_t*)(sm + byo)          = pk2(h0, h1);
            *(uint32_t*)(sm + OFF_AL + byo) = pk2(l0, l1);
        }
        // ---- stage B (112px x 32ci) im2col gather, hi/lo ----
        #pragma unroll
        for (int i = 0; i < 7; ++i) {
            int m = t + i*256;              // 0..1791 pairs
            int px = m % 112, cip = m / 112;
            int r  = px / 56, wc = px - r*56;
            int hh = oh0 + r + kh - 1;
            int ww = wc + kw - 1;
            float v0 = 0.f, v1 = 0.f;
            if ((unsigned)hh < HH && (unsigned)ww < WW) {
                const float* p = xb + hh*WW + ww;
                v0 = p[(size_t)(ci0 + 2*cip    ) * HW];
                v1 = p[(size_t)(ci0 + 2*cip + 1) * HW];
            }
            __nv_bfloat16 h0 = __float2bfloat16(v0);
            __nv_bfloat16 h1 = __float2bfloat16(v1);
            __nv_bfloat16 l0 = __float2bfloat16(v0 - __bfloat162float(h0));
            __nv_bfloat16 l1 = __float2bfloat16(v1 - __bfloat162float(h1));
            uint32_t byo = (uint32_t)(px*STR + cip*4);
            *(uint32_t*)(sm + OFF_BH + byo) = pk2(h0, h1);
            *(uint32_t*)(sm + OFF_BL + byo) = pk2(l0, l1);
        }
        __syncthreads();

        // ---- MMA: 2 k16 steps ----
        #pragma unroll
        for (int ks = 0; ks < 2; ++ks) {
            uint32_t ah[2][4], al[2][4], bh[7][2], bl[7][2];
            #pragma unroll
            for (int mf = 0; mf < 2; ++mf) {
                uint32_t ar = (uint32_t)((wco + mf*16)*STR + ks*32) + aoff;
                ldsm_x4(ah[mf], sb + ar);
                ldsm_x4(al[mf], sb + OFF_AL + ar);
            }
            #pragma unroll
            for (int nf = 0; nf < 6; nf += 2) {
                uint32_t br = (uint32_t)((pxw + nf*8)*STR + ks*32) + boff4;
                uint32_t r4[4];
                ldsm_x4(r4, sb + OFF_BH + br);
                bh[nf][0] = r4[0]; bh[nf][1] = r4[1];
                bh[nf+1][0] = r4[2]; bh[nf+1][1] = r4[3];
                ldsm_x4(r4, sb + OFF_BL + br);
                bl[nf][0] = r4[0]; bl[nf][1] = r4[1];
                bl[nf+1][0] = r4[2]; bl[nf+1][1] = r4[3];
            }
            {
                uint32_t br = (uint32_t)((pxw + 48)*STR + ks*32) + boff2;
                ldsm_x2(bh[6], sb + OFF_BH + br);
                ldsm_x2(bl[6], sb + OFF_BL + br);
            }
            #pragma unroll
            for (int mf = 0; mf < 2; ++mf)
                #pragma unroll
                for (int nf = 0; nf < 7; ++nf) {
                    mma_bf16(d[mf][nf], ah[mf], bh[nf]);
                    mma_bf16(d[mf][nf], al[mf], bh[nf]);
                    mma_bf16(d[mf][nf], ah[mf], bl[nf]);
                }
        }
        __syncthreads();
    }

    // ---- epilogue: D frags -> gmem (warp's px all in one output row) ----
    const int oh = oh0 + (w >> 2);
    #pragma unroll
    for (int mf = 0; mf < 2; ++mf) {
        int co_r = co0 + wco + mf*16 + (L >> 2);
        float* ob = out + (((size_t)b*CO + co_r)*HH + oh)*WW;
        #pragma unroll
        for (int nf = 0; nf < 7; ++nf) {
            int wc = nf*8 + (L & 3)*2;
            float2* o0 = (float2*)(ob + wc);
            float2* o1 = (float2*)(ob + 8*HW + wc);   // co_r + 8
            *o0 = make_float2(d[mf][nf][0], d[mf][nf][1]);
            *o1 = make_float2(d[mf][nf][2], d[mf][nf][3]);
        }
    }
}

// ---------------------------------------------------------------------------
extern "C" void kernel_launch(void* const* d_in, const int* in_sizes, int n_in,
                              void* d_out, int out_size) {
    const float* x     = (const float*)d_in[0];
    const float* convs = (const float*)d_in[1];
    const float* w1    = (const float*)d_in[2];
    const float* b1    = (const float*)d_in[3];
    const float* w2    = (const float*)d_in[4];
    const float* b2    = (const float*)d_in[5];
    float* out = (float*)d_out;

    gap_kernel<<<BN*CI, 256>>>(x);
    rout_kernel<<<1, 32>>>(w1, b1, w2, b2);
    mixT_kernel<<<(BN*CO*CI + 255)/256, 256>>>(convs);
    {
        dim3 grid(28, 2, BN);   // 28 px-tiles x 2 co-blocks x 32 batch
        conv_mma_kernel<<<grid, 256>>>(x, out);
    }
    (void)in_sizes; (void)n_in; (void)out_size;
}

// round 14
// speedup vs baseline: 2.5784x; 1.0976x over previous
#include <cuda_runtime.h>
#include <cuda_bf16.h>
#include <stdint.h>

#define BN   32
#define CI   128
#define CO   256
#define HH   56
#define WW   56
#define EE   4
#define RR   16
#define HW   (HH*WW)        // 3136
#define KVOL 9
#define EOFF (CO*CI*KVOL)

__device__ float g_gap[BN*CI];
__device__ float g_rout[BN*EE];
// pre-split bf16 pair-words: A = weights [b][tap][co][cip0..63], X = input [b][cip0..63][hw]
__device__ uint32_t g_AH[(size_t)BN*KVOL*CO*64];
__device__ uint32_t g_AL[(size_t)BN*KVOL*CO*64];
__device__ uint32_t g_XH[(size_t)BN*64*HW];
__device__ uint32_t g_XL[(size_t)BN*64*HW];

__device__ __forceinline__ uint32_t smem_u32(const void* p) {
    uint32_t a;
    asm("{ .reg .u64 t; cvta.to.shared.u64 t, %1; cvt.u32.u64 %0, t; }"
        : "=r"(a) : "l"(p));
    return a;
}
__device__ __forceinline__ uint32_t pk2(__nv_bfloat16 a, __nv_bfloat16 b) {
    unsigned short x = *(unsigned short*)&a, y = *(unsigned short*)&b;
    return (uint32_t)x | ((uint32_t)y << 16);
}
__device__ __forceinline__ void split2(float v0, float v1, uint32_t& hi, uint32_t& lo) {
    __nv_bfloat16 h0 = __float2bfloat16(v0);
    __nv_bfloat16 h1 = __float2bfloat16(v1);
    __nv_bfloat16 l0 = __float2bfloat16(v0 - __bfloat162float(h0));
    __nv_bfloat16 l1 = __float2bfloat16(v1 - __bfloat162float(h1));
    hi = pk2(h0, h1);
    lo = pk2(l0, l1);
}
__device__ __forceinline__ void ldsm_x4(uint32_t* r, uint32_t addr) {
    asm volatile("ldmatrix.sync.aligned.m8n8.x4.shared.b16 {%0,%1,%2,%3}, [%4];"
        : "=r"(r[0]), "=r"(r[1]), "=r"(r[2]), "=r"(r[3]) : "r"(addr));
}
__device__ __forceinline__ void ldsm_x2(uint32_t* r, uint32_t addr) {
    asm volatile("ldmatrix.sync.aligned.m8n8.x2.shared.b16 {%0,%1}, [%2];"
        : "=r"(r[0]), "=r"(r[1]) : "r"(addr));
}
__device__ __forceinline__ void mma_bf16(float* d, const uint32_t* a, const uint32_t* b) {
    asm volatile("mma.sync.aligned.m16n8k16.row.col.f32.bf16.bf16.f32 "
        "{%0,%1,%2,%3}, {%4,%5,%6,%7}, {%8,%9}, {%0,%1,%2,%3};"
        : "+f"(d[0]), "+f"(d[1]), "+f"(d[2]), "+f"(d[3])
        : "r"(a[0]), "r"(a[1]), "r"(a[2]), "r"(a[3]), "r"(b[0]), "r"(b[1]));
}
__device__ __forceinline__ void cp16(uint32_t dst, const void* src) {
    asm volatile("cp.async.cg.shared.global [%0], [%1], 16;" :: "r"(dst), "l"(src));
}
__device__ __forceinline__ void cp4z(uint32_t dst, const void* src, int src_size) {
    asm volatile("cp.async.ca.shared.global [%0], [%1], 4, %2;"
                 :: "r"(dst), "l"(src), "r"(src_size));
}
__device__ __forceinline__ void cp_commit() {
    asm volatile("cp.async.commit_group;" ::: "memory");
}
template <int N>
__device__ __forceinline__ void cp_wait() {
    asm volatile("cp.async.wait_group %0;" :: "n"(N) : "memory");
}

// ---------------------------------------------------------------------------
// Kernel 1: global average pool
// ---------------------------------------------------------------------------
__global__ void gap_kernel(const float* __restrict__ x) {
    int bc = blockIdx.x;
    const float* p = x + (size_t)bc * HW;
    float s = 0.f;
    for (int i = threadIdx.x; i < HW; i += 256) s += p[i];
    __shared__ float red[256];
    red[threadIdx.x] = s;
    __syncthreads();
    for (int o = 128; o > 0; o >>= 1) {
        if (threadIdx.x < o) red[threadIdx.x] += red[threadIdx.x + o];
        __syncthreads();
    }
    if (threadIdx.x == 0) g_gap[bc] = red[0] * (1.0f / (float)HW);
}

// ---------------------------------------------------------------------------
// Kernel 2: router MLP + softmax(logits/30)
// ---------------------------------------------------------------------------
__global__ void rout_kernel(const float* __restrict__ w1, const float* __restrict__ b1,
                            const float* __restrict__ w2, const float* __restrict__ b2) {
    int b = threadIdx.x;
    if (b >= BN) return;
    float h[RR];
    #pragma unroll
    for (int j = 0; j < RR; ++j) {
        float s = b1[j];
        for (int i = 0; i < CI; ++i) s += w1[j*CI + i] * g_gap[b*CI + i];
        h[j] = fmaxf(s, 0.f);
    }
    float lg[EE];
    float mx = -1e30f;
    #pragma unroll
    for (int e = 0; e < EE; ++e) {
        float s = b2[e];
        #pragma unroll
        for (int j = 0; j < RR; ++j) s += w2[e*RR + j] * h[j];
        lg[e] = s * (1.0f / 30.0f);
        mx = fmaxf(mx, lg[e]);
    }
    float den = 0.f;
    #pragma unroll
    for (int e = 0; e < EE; ++e) { lg[e] = __expf(lg[e] - mx); den += lg[e]; }
    float inv = 1.0f / den;
    #pragma unroll
    for (int e = 0; e < EE; ++e) g_rout[b*EE + e] = lg[e] * inv;
}

// ---------------------------------------------------------------------------
// Kernel 3: mix + split weights -> g_AH/g_AL pair-words.
// Thread owns (co, cip); reads the 4 expert banks once, loops all b.
// ---------------------------------------------------------------------------
__global__ void mixA_kernel(const float* __restrict__ convs) {
    int idx = blockIdx.x * blockDim.x + threadIdx.x;  // over CO*64
    if (idx >= CO*64) return;
    int co  = idx >> 6;
    int cip = idx & 63;
    // expert weights for ci = 2cip, 2cip+1, all taps
    float wv[EE][2][KVOL];
    #pragma unroll
    for (int e = 0; e < EE; ++e) {
        const float* s0 = convs + (size_t)e*EOFF + ((size_t)co*CI + 2*cip)*KVOL;
        #pragma unroll
        for (int tap = 0; tap < KVOL; ++tap) {
            wv[e][0][tap] = s0[tap];
            wv[e][1][tap] = s0[KVOL + tap];
        }
    }
    for (int b = 0; b < BN; ++b) {
        float r0 = g_rout[b*EE+0], r1 = g_rout[b*EE+1];
        float r2 = g_rout[b*EE+2], r3 = g_rout[b*EE+3];
        #pragma unroll
        for (int tap = 0; tap < KVOL; ++tap) {
            float a0 = r0*wv[0][0][tap] + r1*wv[1][0][tap] + r2*wv[2][0][tap] + r3*wv[3][0][tap];
            float a1 = r0*wv[0][1][tap] + r1*wv[1][1][tap] + r2*wv[2][1][tap] + r3*wv[3][1][tap];
            uint32_t hi, lo;
            split2(a0, a1, hi, lo);
            size_t o = (((size_t)b*KVOL + tap)*CO + co)*64 + cip;
            g_AH[o] = hi;
            g_AL[o] = lo;
        }
    }
}

// ---------------------------------------------------------------------------
// Kernel 3b: split x -> g_XH/g_XL pair-words [b][cip][hw]
// ---------------------------------------------------------------------------
__global__ void xcvt_kernel(const float* __restrict__ x) {
    int idx = blockIdx.x * blockDim.x + threadIdx.x;   // over BN*64*HW
    if (idx >= BN*64*HW) return;
    int hw  = idx % HW;
    int rem = idx / HW;
    int cip = rem & 63;
    int b   = rem >> 6;
    const float* p = x + ((size_t)b*CI + 2*cip)*HW + hw;
    uint32_t hi, lo;
    split2(p[0], p[HW], hi, lo);
    g_XH[idx] = hi;
    g_XL[idx] = lo;
}

// ---------------------------------------------------------------------------
// Kernel 4: bf16 mma.sync implicit GEMM, pre-split operands, cp.async
// double-buffered. CTA: 128co x 112px, K-chunk = 16 (72 chunks).
// SMEM/stage: AH|AL (128x48B) + BH|BL (112x48B) = 23040B, 2 stages = 46080B.
// D += Ahi*Bhi + Alo*Bhi + Ahi*Blo.
// ---------------------------------------------------------------------------
#define STR    48
#define AH_O   0
#define AL_O   6144
#define BH_O   12288
#define BL_O   17664
#define STAGE  23040
#define NCH    72

__global__ void __launch_bounds__(256, 2)
conv_mma_kernel(const float* __restrict__ x, float* __restrict__ out) {
    __shared__ __align__(16) unsigned char sm[2*STAGE];

    const int b   = blockIdx.z;
    const int co0 = blockIdx.y * 128;
    const int oh0 = blockIdx.x * 2;
    const int t   = threadIdx.x;
    const int L   = t & 31;
    const int w   = t >> 5;
    const int wco = (w & 3) * 32;
    const int pxw = (w >> 2) * 56;

    const uint32_t sb = smem_u32(sm);
    const uint32_t aoff  = (uint32_t)((L % 16) * STR + (L / 16) * 16);
    const uint32_t boff4 = (uint32_t)(((L & 7) + ((L >> 4) & 1) * 8) * STR + ((L >> 3) & 1) * 16);
    const uint32_t boff2 = (uint32_t)((L & 7) * STR + ((L >> 3) & 1) * 16);

    // per-thread B-gather geometry: wc[0:6], r[7], j[8:11], hl[12], px[16:23]
    uint32_t geo[7];
    #pragma unroll
    for (int i = 0; i < 7; ++i) {
        int m  = t + i*256;
        int px = m % 112, q = m / 112;
        int r  = px / 56, wc = px - r*56;
        geo[i] = (uint32_t)wc | ((uint32_t)r << 7) | ((uint32_t)(q & 7) << 8)
               | ((uint32_t)(q >> 3) << 12) | ((uint32_t)px << 16);
    }

    const int aco  = t >> 1;       // A-stage: co row
    const int ahalf = (t & 1) * 4; // word offset of 16B half

    float d[2][7][4];
    #pragma unroll
    for (int mf = 0; mf < 2; ++mf)
        #pragma unroll
        for (int nf = 0; nf < 7; ++nf)
            #pragma unroll
            for (int k = 0; k < 4; ++k) d[mf][nf][k] = 0.f;

    // ---- staging lambda (chunk cc -> buffer buf) ----
    auto stage = [&](int cc, int buf) {
        const int tap  = cc >> 3;
        const int cip0 = (cc & 7) * 8;
        const int kh = tap / 3, kw = tap - 3*(tap/3);
        const uint32_t sbuf = sb + buf*STAGE;
        // A: 2 x 16B per thread (hi + lo)
        {
            size_t src = (((size_t)b*KVOL + tap)*CO + co0 + aco)*64 + cip0 + ahalf;
            uint32_t dst = sbuf + (uint32_t)(aco*STR) + (uint32_t)(ahalf*4);
            cp16(dst + AH_O, g_AH + src);
            cp16(dst + AL_O, g_AL + src);
        }
        // B: 7 x 4B gather with zero-fill
        #pragma unroll
        for (int i = 0; i < 7; ++i) {
            uint32_t g = geo[i];
            int wc = g & 0x7f, r = (g >> 7) & 1, j = (g >> 8) & 0xf;
            int hl = (g >> 12) & 1, px = (g >> 16) & 0xff;
            int ih = oh0 + r + kh - 1;
            int iw = wc + kw - 1;
            int ok = ((unsigned)ih < HH && (unsigned)iw < WW) ? 4 : 0;
            const uint32_t* arr = hl ? g_XL : g_XH;
            size_t src = ((size_t)b*64 + cip0 + j)*HW + ih*WW + iw;
            if (!ok) src = 0;
            uint32_t dst = sbuf + (hl ? BL_O : BH_O) + (uint32_t)(px*STR + j*4);
            cp4z(dst, arr + src, ok);
        }
    };

    // ---- pipeline ----
    stage(0, 0);
    cp_commit();

    for (int c = 0; c < NCH; ++c) {
        if (c + 1 < NCH) {
            stage(c + 1, (c + 1) & 1);
            cp_commit();
            cp_wait<1>();
        } else {
            cp_wait<0>();
        }
        __syncthreads();

        const uint32_t sbuf = sb + (c & 1)*STAGE;
        uint32_t ah[2][4], al[2][4], bb[7][2];
        #pragma unroll
        for (int mf = 0; mf < 2; ++mf) {
            uint32_t ar = (uint32_t)((wco + mf*16)*STR) + aoff;
            ldsm_x4(ah[mf], sbuf + AH_O + ar);
            ldsm_x4(al[mf], sbuf + AL_O + ar);
        }
        // hi B
        #pragma unroll
        for (int nf = 0; nf < 6; nf += 2) {
            uint32_t br = (uint32_t)((pxw + nf*8)*STR) + boff4;
            uint32_t r4[4];
            ldsm_x4(r4, sbuf + BH_O + br);
            bb[nf][0] = r4[0]; bb[nf][1] = r4[1];
            bb[nf+1][0] = r4[2]; bb[nf+1][1] = r4[3];
        }
        {
            uint32_t br = (uint32_t)((pxw + 48)*STR) + boff2;
            ldsm_x2(bb[6], sbuf + BH_O + br);
        }
        #pragma unroll
        for (int mf = 0; mf < 2; ++mf)
            #pragma unroll
            for (int nf = 0; nf < 7; ++nf) {
                mma_bf16(d[mf][nf], ah[mf], bb[nf]);
                mma_bf16(d[mf][nf], al[mf], bb[nf]);
            }
        // lo B (reuse bb regs)
        #pragma unroll
        for (int nf = 0; nf < 6; nf += 2) {
            uint32_t br = (uint32_t)((pxw + nf*8)*STR) + boff4;
            uint32_t r4[4];
            ldsm_x4(r4, sbuf + BL_O + br);
            bb[nf][0] = r4[0]; bb[nf][1] = r4[1];
            bb[nf+1][0] = r4[2]; bb[nf+1][1] = r4[3];
        }
        {
            uint32_t br = (uint32_t)((pxw + 48)*STR) + boff2;
            ldsm_x2(bb[6], sbuf + BL_O + br);
        }
        #pragma unroll
        for (int mf = 0; mf < 2; ++mf)
            #pragma unroll
            for (int nf = 0; nf < 7; ++nf)
                mma_bf16(d[mf][nf], ah[mf], bb[nf]);

        __syncthreads();
    }

    // ---- epilogue (identical to round-12, verified) ----
    const int oh = oh0 + (w >> 2);
    #pragma unroll
    for (int mf = 0; mf < 2; ++mf) {
        int co_r = co0 + wco + mf*16 + (L >> 2);
        float* ob = out + (((size_t)b*CO + co_r)*HH + oh)*WW;
        #pragma unroll
        for (int nf = 0; nf < 7; ++nf) {
            int wc = nf*8 + (L & 3)*2;
            float2* o0 = (float2*)(ob + wc);
            float2* o1 = (float2*)(ob + 8*HW + wc);
            *o0 = make_float2(d[mf][nf][0], d[mf][nf][1]);
            *o1 = make_float2(d[mf][nf][2], d[mf][nf][3]);
        }
    }
}

// ---------------------------------------------------------------------------
extern "C" void kernel_launch(void* const* d_in, const int* in_sizes, int n_in,
                              void* d_out, int out_size) {
    const float* x     = (const float*)d_in[0];
    const float* convs = (const float*)d_in[1];
    const float* w1    = (const float*)d_in[2];
    const float* b1    = (const float*)d_in[3];
    const float* w2    = (const float*)d_in[4];
    const float* b2    = (const float*)d_in[5];
    float* out = (float*)d_out;

    gap_kernel<<<BN*CI, 256>>>(x);
    rout_kernel<<<1, 32>>>(w1, b1, w2, b2);
    mixA_kernel<<<(CO*64 + 255)/256, 256>>>(convs);
    xcvt_kernel<<<(BN*64*HW + 255)/256, 256>>>(x);
    {
        dim3 grid(28, 2, BN);
        conv_mma_kernel<<<grid, 256>>>(x, out);
    }
    (void)in_sizes; (void)n_in; (void)out_size;
}